// round 8
// baseline (speedup 1.0000x reference)
#include <cuda_runtime.h>

#define NN 50000
#define EE 800000
#define DD 64
#define LL 3
#define RR 4

// ---------------- device scratch (static: no allocations allowed) ----------------
__device__ float g_h[NN * DD];
__device__ float g_xproj[NN * DD];
__device__ float g_p[NN * DD];
__device__ float g_tbar[NN * DD];
__device__ float g_hnew[NN * DD];
__device__ unsigned char g_keepb[LL * NN];
__device__ int g_deg[NN];
__device__ int g_rowptr[NN + 1];
__device__ int g_cursor[NN];
__device__ int g_col[EE];
__device__ int g_partials[64];
__device__ float g_bnsum[DD];
__device__ float g_bnsq[DD];
__device__ float g_bnstats[2 * DD];  // [0..63]=mu, [64..127]=rstd
__device__ int g_is64;

// ---------------- helpers ----------------
__device__ __forceinline__ unsigned rotl32(unsigned v, int s) {
    return (v << s) | (v >> (32 - s));
}

// JAX threefry2x32 (20 rounds), exact
__device__ void threefry(unsigned k0, unsigned k1, unsigned x0, unsigned x1,
                         unsigned& o0, unsigned& o1) {
    unsigned ks2 = k0 ^ k1 ^ 0x1BD11BDAu;
    x0 += k0; x1 += k1;
#define TFR(r) { x0 += x1; x1 = rotl32(x1, r); x1 ^= x0; }
    TFR(13) TFR(15) TFR(26) TFR(6)   x0 += k1;  x1 += ks2 + 1u;
    TFR(17) TFR(29) TFR(16) TFR(24)  x0 += ks2; x1 += k0 + 2u;
    TFR(13) TFR(15) TFR(26) TFR(6)   x0 += k0;  x1 += k1 + 3u;
    TFR(17) TFR(29) TFR(16) TFR(24)  x0 += k1;  x1 += ks2 + 4u;
    TFR(13) TFR(15) TFR(26) TFR(6)   x0 += ks2; x1 += k0 + 5u;
#undef TFR
    o0 = x0; o1 = x1;
}

__device__ __forceinline__ float mishf(float x) {
    float sp = fmaxf(x, 0.f) + log1pf(expf(-fabsf(x)));
    return x * tanhf(sp);
}

__device__ __forceinline__ int edge_val(const void* ei, int idx) {
    if (g_is64) return (int)((const long long*)ei)[idx];
    return ((const int*)ei)[idx];
}

// ---------------- init / dtype detect ----------------
__global__ void init_kernel() {
    int i = blockIdx.x * blockDim.x + threadIdx.x;
    if (i < NN) g_deg[i] = 0;
    if (i == 0) g_is64 = 1;
}

// If edge_index is int64, odd 32-bit words (hi halves) are all 0 (values < 50000).
// If int32, odd words are node ids (mostly nonzero). Reads stay within the
// smaller (int32) buffer size: max word index = 2*EE-1.
__global__ void detect_kernel(const unsigned* w) {
    int i = blockIdx.x * blockDim.x + threadIdx.x;
    if (i < EE) {
        if (w[2 * i + 1] != 0u) g_is64 = 0;
    }
}

// ---------------- dropout masks ----------------
// jax_threefry_partitionable=True (modern default) random_bits, bit_width=32:
//   counter for flat index f: (hi, lo) = (f >> 32, (uint32)f)
//   (o0, o1) = threefry(key, hi, lo)
//   32-bit draw = o0 ^ o1          <-- NOT truncation (that's only for bit_width 64)
// u = bitcast(draw >> 9 | 0x3f800000) - 1;  bernoulli = (u < 0.2);  keep = !bernoulli.
// fold_in: folded_key = threefry((0,42), 0, layer).
__global__ void mask_kernel() {
    int i = blockIdx.x * blockDim.x + threadIdx.x;
    if (i >= LL * NN) return;
    int lay = i / NN, n = i % NN;
    unsigned fk0, fk1;
    threefry(0u, 42u, 0u, (unsigned)lay, fk0, fk1);  // fold_in(key(42), lay)
    unsigned byte = 0;
#pragma unroll
    for (int r = 0; r < RR; r++) {
        unsigned o0, o1;
        threefry(fk0, fk1, 0u, (unsigned)(r * NN + n), o0, o1);
        unsigned draw = o0 ^ o1;
        float u = __uint_as_float((draw >> 9) | 0x3f800000u) - 1.0f;
        if (!(u < 0.2f)) byte |= (1u << r);
    }
    g_keepb[i] = (unsigned char)byte;
}

// ---------------- CSR build ----------------
__global__ void count_deg(const void* ei) {
    int e = blockIdx.x * blockDim.x + threadIdx.x;
    if (e < EE) atomicAdd(&g_deg[edge_val(ei, EE + e)], 1);
}

__global__ void scan1() {
    __shared__ int s[256];
    int t = threadIdx.x;
    int base = blockIdx.x * 1024 + t * 4;
    int v0 = (base + 0 < NN) ? g_deg[base + 0] : 0;
    int v1 = (base + 1 < NN) ? g_deg[base + 1] : 0;
    int v2 = (base + 2 < NN) ? g_deg[base + 2] : 0;
    int v3 = (base + 3 < NN) ? g_deg[base + 3] : 0;
    int sum = v0 + v1 + v2 + v3;
    s[t] = sum;
    __syncthreads();
#pragma unroll
    for (int off = 1; off < 256; off <<= 1) {
        int x = (t >= off) ? s[t - off] : 0;
        __syncthreads();
        s[t] += x;
        __syncthreads();
    }
    int excl = s[t] - sum;
    if (base + 0 < NN) g_rowptr[base + 0] = excl;
    if (base + 1 < NN) g_rowptr[base + 1] = excl + v0;
    if (base + 2 < NN) g_rowptr[base + 2] = excl + v0 + v1;
    if (base + 3 < NN) g_rowptr[base + 3] = excl + v0 + v1 + v2;
    if (t == 255) g_partials[blockIdx.x] = s[255];
}

__global__ void scan2() {
    __shared__ int s[64];
    int t = threadIdx.x;
    int v = (t < 49) ? g_partials[t] : 0;
    s[t] = v;
    __syncthreads();
#pragma unroll
    for (int off = 1; off < 64; off <<= 1) {
        int x = (t >= off) ? s[t - off] : 0;
        __syncthreads();
        s[t] += x;
        __syncthreads();
    }
    g_partials[t] = s[t] - v;
    if (t == 63) g_rowptr[NN] = s[63];
}

__global__ void scan3() {
    int i = blockIdx.x * blockDim.x + threadIdx.x;
    if (i < NN) {
        int v = g_rowptr[i] + g_partials[i >> 10];
        g_rowptr[i] = v;
        g_cursor[i] = v;
    }
}

__global__ void fill_csr(const void* ei) {
    int e = blockIdx.x * blockDim.x + threadIdx.x;
    if (e < EE) {
        int dst = edge_val(ei, EE + e);
        int src = edge_val(ei, e);
        int pos = atomicAdd(&g_cursor[dst], 1);
        g_col[pos] = src;
    }
}

// ---------------- GEMM (M x 64) @ (64 x 64), fused epilogues ----------------
// mode 0: Y = X@W            (p = h@W1, bias deferred)
// mode 1: Y = X@W + b        (x_proj)
// mode 2: Y = mish(X@W + b)  (node MLP hidden)
// mode 3: Y = X@W + b + res  (hnew = tbar@W2+b2+h)  + batchnorm partial sums
__global__ __launch_bounds__(256) void gemm64(
    const float* __restrict__ X, const float* __restrict__ W,
    const float* __restrict__ bias, const float* __restrict__ res,
    float* __restrict__ Y, int M, int mode) {
    __shared__ float Xs[64 * 64];
    __shared__ float Ws[64 * 64];
    __shared__ float s_sum[64];
    __shared__ float s_sq[64];
    int t = threadIdx.x;
    int row0 = blockIdx.x * 64;
    const float4* W4 = (const float4*)W;
    float4* Ws4 = (float4*)Ws;
#pragma unroll
    for (int i = 0; i < 4; i++) Ws4[t + 256 * i] = W4[t + 256 * i];
    const float4* X4 = (const float4*)X;
    float4* Xs4 = (float4*)Xs;
#pragma unroll
    for (int i = 0; i < 4; i++) {
        int idx = t + 256 * i;
        int r = row0 + (idx >> 4);
        Xs4[idx] = (r < M) ? X4[r * 16 + (idx & 15)] : make_float4(0.f, 0.f, 0.f, 0.f);
    }
    if (mode == 3 && t < 64) { s_sum[t] = 0.f; s_sq[t] = 0.f; }
    __syncthreads();
    int tx = t & 15, ty = t >> 4;
    float acc[4][4];
#pragma unroll
    for (int i = 0; i < 4; i++)
        acc[i][0] = acc[i][1] = acc[i][2] = acc[i][3] = 0.f;
#pragma unroll 8
    for (int k = 0; k < 64; k++) {
        float4 w = Ws4[k * 16 + tx];
#pragma unroll
        for (int i = 0; i < 4; i++) {
            float xv = Xs[(ty * 4 + i) * 64 + k];
            acc[i][0] = fmaf(xv, w.x, acc[i][0]);
            acc[i][1] = fmaf(xv, w.y, acc[i][1]);
            acc[i][2] = fmaf(xv, w.z, acc[i][2]);
            acc[i][3] = fmaf(xv, w.w, acc[i][3]);
        }
    }
    float4 b = bias ? ((const float4*)bias)[tx] : make_float4(0.f, 0.f, 0.f, 0.f);
    float4* Y4 = (float4*)Y;
    const float4* R4 = (const float4*)res;
    float lsum[4] = {0.f, 0.f, 0.f, 0.f}, lsq[4] = {0.f, 0.f, 0.f, 0.f};
#pragma unroll
    for (int i = 0; i < 4; i++) {
        int r = row0 + ty * 4 + i;
        if (r >= M) break;
        float4 y;
        y.x = acc[i][0] + b.x; y.y = acc[i][1] + b.y;
        y.z = acc[i][2] + b.z; y.w = acc[i][3] + b.w;
        if (mode == 2) {
            y.x = mishf(y.x); y.y = mishf(y.y);
            y.z = mishf(y.z); y.w = mishf(y.w);
        }
        if (mode == 3) {
            float4 rr = R4[r * 16 + tx];
            y.x += rr.x; y.y += rr.y; y.z += rr.z; y.w += rr.w;
            lsum[0] += y.x; lsum[1] += y.y; lsum[2] += y.z; lsum[3] += y.w;
            lsq[0] += y.x * y.x; lsq[1] += y.y * y.y;
            lsq[2] += y.z * y.z; lsq[3] += y.w * y.w;
        }
        Y4[r * 16 + tx] = y;
    }
    if (mode == 3) {
        int c0 = tx * 4;
#pragma unroll
        for (int j = 0; j < 4; j++) {
            atomicAdd(&s_sum[c0 + j], lsum[j]);
            atomicAdd(&s_sq[c0 + j], lsq[j]);
        }
        __syncthreads();
        if (t < 64) {
            atomicAdd(&g_bnsum[t], s_sum[t]);
            atomicAdd(&g_bnsq[t], s_sq[t]);
        }
    }
}

// ---------------- aggregation in p-space, fused mish + replica mean ----------------
// One warp per node; lane handles 2 features (float2).
// z_r[n] = keep_r[n]*p[n] + sum_{e->n} keep_r[src]*p[src];  tbar = mean_r mish(z_r+b1)
__global__ __launch_bounds__(256) void agg_kernel(
    const float2* __restrict__ p2, const unsigned char* __restrict__ keepb,
    const float* __restrict__ b1, float2* __restrict__ tbar) {
    int gt = blockIdx.x * blockDim.x + threadIdx.x;
    int n = gt >> 5;
    int lane = gt & 31;
    if (n >= NN) return;
    unsigned mb = keepb[n];
    float2 vs = p2[n * 32 + lane];
    float2 a0, a1, a2, a3;
    a0.x = (mb & 1u) ? vs.x : 0.f; a0.y = (mb & 1u) ? vs.y : 0.f;
    a1.x = (mb & 2u) ? vs.x : 0.f; a1.y = (mb & 2u) ? vs.y : 0.f;
    a2.x = (mb & 4u) ? vs.x : 0.f; a2.y = (mb & 4u) ? vs.y : 0.f;
    a3.x = (mb & 8u) ? vs.x : 0.f; a3.y = (mb & 8u) ? vs.y : 0.f;
    int j = g_rowptr[n], end = g_rowptr[n + 1];
    for (; j < end; j++) {
        int s = g_col[j];
        unsigned m = keepb[s];
        float2 v = p2[s * 32 + lane];
        if (m & 1u) { a0.x += v.x; a0.y += v.y; }
        if (m & 2u) { a1.x += v.x; a1.y += v.y; }
        if (m & 4u) { a2.x += v.x; a2.y += v.y; }
        if (m & 8u) { a3.x += v.x; a3.y += v.y; }
    }
    float bx = b1[2 * lane], by = b1[2 * lane + 1];
    float sx = mishf(a0.x + bx) + mishf(a1.x + bx) + mishf(a2.x + bx) + mishf(a3.x + bx);
    float sy = mishf(a0.y + by) + mishf(a1.y + by) + mishf(a2.y + by) + mishf(a3.y + by);
    float2 o;
    o.x = 0.25f * sx;
    o.y = 0.25f * sy;
    tbar[n * 32 + lane] = o;
}

// ---------------- batchnorm ----------------
__global__ void zero_bn() {
    int t = threadIdx.x;
    if (t < 64) { g_bnsum[t] = 0.f; g_bnsq[t] = 0.f; }
}

__global__ void bn_final() {
    int d = threadIdx.x;  // 64
    float mu = g_bnsum[d] * (1.f / NN);
    float var = g_bnsq[d] * (1.f / NN) - mu * mu;
    g_bnstats[d] = mu;
    g_bnstats[64 + d] = rsqrtf(var + 1e-5f);
}

__global__ void bn_apply(float* __restrict__ dst, int last) {
    int i = blockIdx.x * blockDim.x + threadIdx.x;
    if (i >= NN * DD) return;
    int d = i & 63;
    float v = (g_hnew[i] - g_bnstats[d]) * g_bnstats[64 + d];
    v = mishf(v);
    dst[i] = last ? (g_xproj[i] + v) : v;
}

__global__ void copy_h_from_xproj() {
    int i = blockIdx.x * blockDim.x + threadIdx.x;
    if (i < NN * 16) ((float4*)g_h)[i] = ((const float4*)g_xproj)[i];
}

// ---------------- launch ----------------
extern "C" void kernel_launch(void* const* d_in, const int* in_sizes, int n_in,
                              void* d_out, int out_size) {
    const float* x    = (const float*)d_in[0];
    const void*  ei   = d_in[1];  // int32 or int64, auto-detected on device
    const float* nW1  = (const float*)d_in[2];
    const float* nb1  = (const float*)d_in[3];
    const float* nW2  = (const float*)d_in[4];
    const float* nb2  = (const float*)d_in[5];
    const float* cW1  = (const float*)d_in[6];
    const float* cb1  = (const float*)d_in[7];
    const float* cW2  = (const float*)d_in[8];
    const float* cb2  = (const float*)d_in[9];
    float* out = (float*)d_out;

    float *h, *xproj, *p, *tbar, *hnew;
    unsigned char* keepb;
    cudaGetSymbolAddress((void**)&h, g_h);
    cudaGetSymbolAddress((void**)&xproj, g_xproj);
    cudaGetSymbolAddress((void**)&p, g_p);
    cudaGetSymbolAddress((void**)&tbar, g_tbar);
    cudaGetSymbolAddress((void**)&hnew, g_hnew);
    cudaGetSymbolAddress((void**)&keepb, g_keepb);

    const int TB = 256;
    init_kernel<<<(NN + TB - 1) / TB, TB>>>();
    detect_kernel<<<(EE + TB - 1) / TB, TB>>>((const unsigned*)ei);
    count_deg<<<(EE + TB - 1) / TB, TB>>>(ei);
    scan1<<<49, 256>>>();
    scan2<<<1, 64>>>();
    scan3<<<(NN + TB - 1) / TB, TB>>>();
    fill_csr<<<(EE + TB - 1) / TB, TB>>>(ei);
    mask_kernel<<<(LL * NN + TB - 1) / TB, TB>>>();

    int GB = (NN + 63) / 64;
    // node MLP: p <- mish(x@nW1+nb1); xproj <- p@nW2+nb2; h <- xproj
    gemm64<<<GB, 256>>>(x, nW1, nb1, nullptr, p, NN, 2);
    gemm64<<<GB, 256>>>(p, nW2, nb2, nullptr, xproj, NN, 1);
    copy_h_from_xproj<<<(NN * 16 + TB - 1) / TB, TB>>>();

    for (int l = 0; l < LL; l++) {
        zero_bn<<<1, 64>>>();
        gemm64<<<GB, 256>>>(h, cW1 + l * DD * DD, nullptr, nullptr, p, NN, 0);
        agg_kernel<<<(NN * 32 + TB - 1) / TB, TB>>>(
            (const float2*)p, keepb + l * NN, cb1 + l * DD, (float2*)tbar);
        gemm64<<<GB, 256>>>(tbar, cW2 + l * DD * DD, cb2 + l * DD, h, hnew, NN, 3);
        bn_final<<<1, 64>>>();
        bn_apply<<<(NN * DD + TB - 1) / TB, TB>>>((l == LL - 1) ? out : h,
                                                  (l == LL - 1) ? 1 : 0);
    }
}